// round 13
// baseline (speedup 1.0000x reference)
#include <cuda_runtime.h>
#include <cuda_bf16.h>
#include <cstdint>

// DynamicSparseAttention: B=4,H=16,S=2048,D=64
// d_out layout (f32): [out: BH*S*D][attn: BH*S*S][tau: BH*S]
#define S_LEN 2048
#define D_DIM 64
#define BH    64
#define NELEM (BH * S_LEN * D_DIM)                 // 8388608
#define SELEM ((size_t)BH * S_LEN * S_LEN)         // 268435456

// pre-split bf16 hi/lo scratch (device globals: allocation-free scratch)
__device__ __align__(16) __nv_bfloat16 g_qhi[NELEM];
__device__ __align__(16) __nv_bfloat16 g_qlo[NELEM];
__device__ __align__(16) __nv_bfloat16 g_khi[NELEM];
__device__ __align__(16) __nv_bfloat16 g_klo[NELEM];
__device__ __align__(16) __nv_bfloat16 g_vhi[NELEM];
__device__ __align__(16) __nv_bfloat16 g_vlo[NELEM];
// scores/exp hi/lo scratch in FRAGMENT-NATIVE layout (see fid below)
__device__ __align__(16) __nv_bfloat16 g_shi[SELEM];
__device__ __align__(16) __nv_bfloat16 g_slo[SELEM];
// per-row 1/denominator
__device__ float g_rd[BH * S_LEN];

// ---------------------------------------------------------------- helpers
__device__ __forceinline__ uint32_t smem_u32(const void* p) {
    uint32_t a;
    asm("{ .reg .u64 t; cvta.to.shared.u64 t, %1; cvt.u32.u64 %0, t; }"
        : "=r"(a) : "l"(p));
    return a;
}

// 128B-row tile, 16B-chunk XOR swizzle
__device__ __forceinline__ uint32_t toff(int r, int ch) {
    return (uint32_t)(r * 128 + ((ch ^ (r & 7)) << 4));
}

__device__ __forceinline__ void ldmx4(uint32_t* r, uint32_t a) {
    asm volatile("ldmatrix.sync.aligned.m8n8.x4.shared.b16 {%0,%1,%2,%3}, [%4];"
        : "=r"(r[0]), "=r"(r[1]), "=r"(r[2]), "=r"(r[3]) : "r"(a));
}
__device__ __forceinline__ void ldmx4t(uint32_t* r, uint32_t a) {
    asm volatile("ldmatrix.sync.aligned.m8n8.x4.trans.shared.b16 {%0,%1,%2,%3}, [%4];"
        : "=r"(r[0]), "=r"(r[1]), "=r"(r[2]), "=r"(r[3]) : "r"(a));
}
__device__ __forceinline__ void mma_bf16(float* c, const uint32_t* a, const uint32_t* b) {
    asm volatile(
        "mma.sync.aligned.m16n8k16.row.col.f32.bf16.bf16.f32 "
        "{%0,%1,%2,%3}, {%4,%5,%6,%7}, {%8,%9}, {%0,%1,%2,%3};"
        : "+f"(c[0]), "+f"(c[1]), "+f"(c[2]), "+f"(c[3])
        : "r"(a[0]), "r"(a[1]), "r"(a[2]), "r"(a[3]), "r"(b[0]), "r"(b[1]));
}

__device__ __forceinline__ void cpa16(uint32_t dst, const void* src) {
    asm volatile("cp.async.cg.shared.global [%0], [%1], 16;"
                 :: "r"(dst), "l"(__cvta_generic_to_global(src)));
}
__device__ __forceinline__ void cpa_commit() {
    asm volatile("cp.async.commit_group;");
}
template <int N>
__device__ __forceinline__ void cpa_wait() {
    asm volatile("cp.async.wait_group %0;" :: "n"(N));
}

__device__ __forceinline__ uint32_t bfpair(float a, float b) {
    __nv_bfloat162 t;
    t.x = __float2bfloat16(a);
    t.y = __float2bfloat16(b);
    return *reinterpret_cast<uint32_t*>(&t);
}
__device__ __forceinline__ float2 bf2f2(uint32_t u) {
    __nv_bfloat162 t = *reinterpret_cast<__nv_bfloat162*>(&u);
    return make_float2(__bfloat162float(t.x), __bfloat162float(t.y));
}
// split pair of floats into hi uint32 + lo(residual) uint32
__device__ __forceinline__ void split2(float a, float b, uint32_t& h, uint32_t& l) {
    __nv_bfloat16 ha = __float2bfloat16(a), hb = __float2bfloat16(b);
    __nv_bfloat162 hp; hp.x = ha; hp.y = hb;
    h = *reinterpret_cast<uint32_t*>(&hp);
    l = bfpair(a - __bfloat162float(ha), b - __bfloat162float(hb));
}
__device__ __forceinline__ void split4(float4 f, uint2& hi, uint2& lo) {
    split2(f.x, f.y, hi.x, lo.x);
    split2(f.z, f.w, hi.y, lo.y);
}
__device__ __forceinline__ float2 rec2(uint32_t h, uint32_t l) {
    float2 a = bf2f2(h), b = bf2f2(l);
    return make_float2(a.x + b.x, a.y + b.y);
}

// -------------------------------------------------------------------------
// Kernel 0: pre-split Q*0.125, K, V into bf16 hi/lo scratch.
// -------------------------------------------------------------------------
__global__ __launch_bounds__(256) void dsa_prep(
    const float* __restrict__ q, const float* __restrict__ k,
    const float* __restrict__ v)
{
    const int stride = gridDim.x * 256;
    const float4* q4 = (const float4*)q;
    const float4* k4 = (const float4*)k;
    const float4* v4 = (const float4*)v;
    uint2* qh = (uint2*)g_qhi; uint2* ql = (uint2*)g_qlo;
    uint2* kh = (uint2*)g_khi; uint2* kl = (uint2*)g_klo;
    uint2* vh = (uint2*)g_vhi; uint2* vl = (uint2*)g_vlo;

    for (int i = blockIdx.x * 256 + threadIdx.x; i < NELEM / 4; i += stride) {
        float4 fq = q4[i];
        fq.x *= 0.125f; fq.y *= 0.125f; fq.z *= 0.125f; fq.w *= 0.125f;
        uint2 hi, lo;
        split4(fq, hi, lo); qh[i] = hi; ql[i] = lo;
        split4(k4[i], hi, lo); kh[i] = hi; kl[i] = lo;
        split4(v4[i], hi, lo); vh[i] = hi; vl[i] = lo;
    }
}

// -------------------------------------------------------------------------
// Fragment-native scratch layout:
//   fid(bh, rb, kb) = ((bh*128 + rb)*128 + kb), rb = qrow/16, kb = kcol/16.
//   uint4 slot: U4[fid*32 + lane] = (w_r_cb0, w_r8_cb0, w_r_cb1, w_r8_cb1)
//   where w = bf16 pair of cols (lane%4)*2,+1; rows r = lane/4, r8 = r+8.
//   This is simultaneously the mma C-frag layout (producer) and the
//   mma A-frag (a0,a1,a2,a3) layout for m16n8k16 (consumer).
// -------------------------------------------------------------------------

// -------------------------------------------------------------------------
// Kernel 1 (FUSED scores + variance + softmax):
//   CTA = 128-row q-stripe (512 thr, 16 warps 4m x 4n, warp tile 32x32).
//   P1: QK^T mainloop (cp.async double-buffered K, A-frags cached in regs),
//       write raw scores hi/lo fragment-native (STG.128), track row stats.
//   P2: re-read own fragments (L2-hot), exp((s-max)*itau), accumulate
//       denominator, overwrite fragments in place with exp hi/lo.
//   P3: re-read exp fragments, write f32 attn = exp * (1/den), store 1/den.
// -------------------------------------------------------------------------
#define FS_SMEM 105984
#define OF_SUM  98304
#define OF_SQ   100352
#define OF_MAX  102400
#define OF_ITAU 104448
#define OF_MX   104960
#define OF_RD   105472

__global__ __launch_bounds__(512) void dsa_fused(
    float* __restrict__ attn, float* __restrict__ tau_out)
{
    extern __shared__ __align__(16) char sm[];
    const uint32_t sb = smem_u32(sm);
    const uint32_t QHI = 0, QLO = 16384;      // K bufs at 32768 + b*32768

    const int tid = threadIdx.x, lane = tid & 31, wid = tid >> 5;
    const int qt = blockIdx.x, bh = blockIdx.y;

    const __nv_bfloat16* Qh = g_qhi + ((size_t)bh * S_LEN + (size_t)qt * 128) * D_DIM;
    const __nv_bfloat16* Ql = g_qlo + ((size_t)bh * S_LEN + (size_t)qt * 128) * D_DIM;
    const __nv_bfloat16* Kh = g_khi + (size_t)bh * S_LEN * D_DIM;
    const __nv_bfloat16* Kl = g_klo + (size_t)bh * S_LEN * D_DIM;

    // group 0: Q hi/lo + K tile 0
    #pragma unroll
    for (int i = 0; i < 2; i++) {
        int idx = tid + i * 512;
        int r = idx >> 3, ch = idx & 7;
        uint32_t o = toff(r, ch);
        cpa16(sb + QHI + o, Qh + r * 64 + ch * 8);
        cpa16(sb + QLO + o, Ql + r * 64 + ch * 8);
        cpa16(sb + 32768 + o, Kh + r * 64 + ch * 8);
        cpa16(sb + 32768 + 16384 + o, Kl + r * 64 + ch * 8);
    }
    cpa_commit();
    // group 1: K tile 1
    #pragma unroll
    for (int i = 0; i < 2; i++) {
        int idx = tid + i * 512;
        int r = idx >> 3, ch = idx & 7;
        uint32_t o = toff(r, ch);
        cpa16(sb + 65536 + o, Kh + (size_t)(128 + r) * 64 + ch * 8);
        cpa16(sb + 65536 + 16384 + o, Kl + (size_t)(128 + r) * 64 + ch * 8);
    }
    cpa_commit();
    cpa_wait<1>();
    __syncthreads();

    const int wm = wid >> 2, wn = wid & 3;
    const int alr = lane & 7, alm = (lane >> 3) & 1, alk = lane >> 4;
    const int brow_off = ((lane >> 4) << 3) + (lane & 7);
    const int bchk_off = (lane >> 3) & 1;

    // A fragments cached in registers for the whole pass 1
    uint32_t ah[4][2][4], al[4][2][4];
    #pragma unroll
    for (int ks = 0; ks < 4; ks++)
        #pragma unroll
        for (int mi = 0; mi < 2; mi++) {
            int row = wm * 32 + mi * 16 + alr + alm * 8;
            uint32_t o = toff(row, ks * 2 + alk);
            ldmx4(ah[ks][mi], sb + QHI + o);
            ldmx4(al[ks][mi], sb + QLO + o);
        }

    uint4* UH = (uint4*)g_shi;
    uint4* UL = (uint4*)g_slo;
    const size_t fb = ((size_t)bh * 128 + (size_t)qt * 8 + wm * 2) * 128;

    // per-lane running stats: [mi][half]  half 0 = row r, 1 = row r+8
    float st_s[2][2] = {}, st_q[2][2] = {};
    float st_m[2][2] = {{-3.402823466e38f, -3.402823466e38f},
                        {-3.402823466e38f, -3.402823466e38f}};

    // ---------------- Pass 1 ----------------
    for (int t = 0; t < 16; t++) {
        const uint32_t KB = sb + 32768 + (uint32_t)(t & 1) * 32768;

        float acc[2][4][4] = {};
        #pragma unroll
        for (int ks = 0; ks < 4; ks++) {
            uint32_t bh_[2][4], bl_[2][4];
            #pragma unroll
            for (int nj = 0; nj < 2; nj++) {
                int row = wn * 32 + nj * 16 + brow_off;
                uint32_t o = toff(row, ks * 2 + bchk_off);
                ldmx4(bh_[nj], KB + o);
                ldmx4(bl_[nj], KB + 16384 + o);
            }
            #pragma unroll
            for (int mi = 0; mi < 2; mi++)
                #pragma unroll
                for (int nj = 0; nj < 2; nj++) {
                    mma_bf16(acc[mi][2*nj],   ah[ks][mi], bh_[nj]);
                    mma_bf16(acc[mi][2*nj+1], ah[ks][mi], bh_[nj] + 2);
                }
            #pragma unroll
            for (int mi = 0; mi < 2; mi++)
                #pragma unroll
                for (int nj = 0; nj < 2; nj++) {
                    mma_bf16(acc[mi][2*nj],   ah[ks][mi], bl_[nj]);
                    mma_bf16(acc[mi][2*nj+1], ah[ks][mi], bl_[nj] + 2);
                }
            #pragma unroll
            for (int mi = 0; mi < 2; mi++)
                #pragma unroll
                for (int nj = 0; nj < 2; nj++) {
                    mma_bf16(acc[mi][2*nj],   al[ks][mi], bh_[nj]);
                    mma_bf16(acc[mi][2*nj+1], al[ks][mi], bh_[nj] + 2);
                }
        }

        // stats + fragment-native hi/lo stores
        #pragma unroll
        for (int mi = 0; mi < 2; mi++) {
            #pragma unroll
            for (int ni = 0; ni < 4; ni++) {
                float a0 = acc[mi][ni][0], a1 = acc[mi][ni][1];
                float a2 = acc[mi][ni][2], a3 = acc[mi][ni][3];
                st_s[mi][0] += a0 + a1;
                st_s[mi][1] += a2 + a3;
                st_q[mi][0] = fmaf(a0, a0, fmaf(a1, a1, st_q[mi][0]));
                st_q[mi][1] = fmaf(a2, a2, fmaf(a3, a3, st_q[mi][1]));
                st_m[mi][0] = fmaxf(st_m[mi][0], fmaxf(a0, a1));
                st_m[mi][1] = fmaxf(st_m[mi][1], fmaxf(a2, a3));
            }
            #pragma unroll
            for (int nj = 0; nj < 2; nj++) {
                uint32_t hx, lx, hy, ly, hz, lz, hw, lw;
                split2(acc[mi][2*nj][0],   acc[mi][2*nj][1],   hx, lx);
                split2(acc[mi][2*nj][2],   acc[mi][2*nj][3],   hy, ly);
                split2(acc[mi][2*nj+1][0], acc[mi][2*nj+1][1], hz, lz);
                split2(acc[mi][2*nj+1][2], acc[mi][2*nj+1][3], hw, lw);
                size_t ad = (fb + (size_t)mi * 128 + t * 8 + wn * 2 + nj) * 32 + lane;
                UH[ad] = make_uint4(hx, hy, hz, hw);
                UL[ad] = make_uint4(lx, ly, lz, lw);
            }
        }
        __syncthreads();   // all reads of K buf[t&1] done before refill

        if (t + 2 < 16) {
            const __nv_bfloat16* th = Kh + (size_t)(t + 2) * 128 * 64;
            const __nv_bfloat16* tl = Kl + (size_t)(t + 2) * 128 * 64;
            uint32_t dst = sb + 32768 + (uint32_t)(t & 1) * 32768;
            #pragma unroll
            for (int i = 0; i < 2; i++) {
                int idx = tid + i * 512;
                int r = idx >> 3, ch = idx & 7;
                uint32_t o = toff(r, ch);
                cpa16(dst + o, th + r * 64 + ch * 8);
                cpa16(dst + 16384 + o, tl + r * 64 + ch * 8);
            }
            cpa_commit();
            cpa_wait<1>();
        } else {
            cpa_wait<0>();
        }
        __syncthreads();
    }

    // ---------------- stats reduction -> tau/itau/max ----------------
    #pragma unroll
    for (int o = 1; o <= 2; o <<= 1) {
        #pragma unroll
        for (int mi = 0; mi < 2; mi++)
            #pragma unroll
            for (int h = 0; h < 2; h++) {
                st_s[mi][h] += __shfl_xor_sync(0xffffffffu, st_s[mi][h], o);
                st_q[mi][h] += __shfl_xor_sync(0xffffffffu, st_q[mi][h], o);
                st_m[mi][h] = fmaxf(st_m[mi][h],
                                    __shfl_xor_sync(0xffffffffu, st_m[mi][h], o));
            }
    }
    float* sSum  = (float*)(sm + OF_SUM);
    float* sSq   = (float*)(sm + OF_SQ);
    float* sMax  = (float*)(sm + OF_MAX);
    float* sItau = (float*)(sm + OF_ITAU);
    float* sMx   = (float*)(sm + OF_MX);
    float* sRd   = (float*)(sm + OF_RD);

    if ((lane & 3) == 0) {
        #pragma unroll
        for (int mi = 0; mi < 2; mi++)
            #pragma unroll
            for (int h = 0; h < 2; h++) {
                int row = wm * 32 + mi * 16 + (lane >> 2) + h * 8;
                sSum[wn * 128 + row] = st_s[mi][h];
                sSq [wn * 128 + row] = st_q[mi][h];
                sMax[wn * 128 + row] = st_m[mi][h];
            }
    }
    __syncthreads();
    if (tid < 128) {
        float S = sSum[tid] + sSum[128 + tid] + sSum[256 + tid] + sSum[384 + tid];
        float Q = sSq[tid]  + sSq[128 + tid]  + sSq[256 + tid]  + sSq[384 + tid];
        float M = fmaxf(fmaxf(sMax[tid], sMax[128 + tid]),
                        fmaxf(sMax[256 + tid], sMax[384 + tid]));
        float mean = S * (1.0f / S_LEN);
        float var  = (Q - S * mean) * (1.0f / (S_LEN - 1));   // ddof=1
        float tau  = fmaxf(1.0f / (1.0f + var), 0.3f);        // BASE=1, MIN=0.3
        sItau[tid] = 1.0f / tau;
        sMx[tid]   = M;
        tau_out[(size_t)bh * S_LEN + (size_t)qt * 128 + tid] = tau;
    }
    __syncthreads();

    // ---------------- Pass 2: exp + denominator (in-place) ----------------
    float itau_[2][2], mxv_[2][2];
    #pragma unroll
    for (int mi = 0; mi < 2; mi++)
        #pragma unroll
        for (int h = 0; h < 2; h++) {
            int row = wm * 32 + mi * 16 + (lane >> 2) + h * 8;
            itau_[mi][h] = sItau[row];
            mxv_[mi][h]  = sMx[row];
        }

    float den[2][2] = {};
    for (int t = 0; t < 16; t++) {
        #pragma unroll
        for (int mi = 0; mi < 2; mi++)
            #pragma unroll
            for (int nj = 0; nj < 2; nj++) {
                size_t ad = (fb + (size_t)mi * 128 + t * 8 + wn * 2 + nj) * 32 + lane;
                uint4 H = UH[ad], L = UL[ad];
                float2 v0 = rec2(H.x, L.x);
                float2 v1 = rec2(H.y, L.y);
                float2 v2 = rec2(H.z, L.z);
                float2 v3 = rec2(H.w, L.w);
                float i0 = itau_[mi][0], m0 = mxv_[mi][0];
                float i1 = itau_[mi][1], m1 = mxv_[mi][1];
                v0.x = __expf((v0.x - m0) * i0); v0.y = __expf((v0.y - m0) * i0);
                v2.x = __expf((v2.x - m0) * i0); v2.y = __expf((v2.y - m0) * i0);
                v1.x = __expf((v1.x - m1) * i1); v1.y = __expf((v1.y - m1) * i1);
                v3.x = __expf((v3.x - m1) * i1); v3.y = __expf((v3.y - m1) * i1);
                den[mi][0] += v0.x + v0.y + v2.x + v2.y;
                den[mi][1] += v1.x + v1.y + v3.x + v3.y;
                uint32_t hx, lx, hy, ly, hz, lz, hw, lw;
                split2(v0.x, v0.y, hx, lx);
                split2(v1.x, v1.y, hy, ly);
                split2(v2.x, v2.y, hz, lz);
                split2(v3.x, v3.y, hw, lw);
                UH[ad] = make_uint4(hx, hy, hz, hw);
                UL[ad] = make_uint4(lx, ly, lz, lw);
            }
    }
    #pragma unroll
    for (int o = 1; o <= 2; o <<= 1) {
        #pragma unroll
        for (int mi = 0; mi < 2; mi++)
            #pragma unroll
            for (int h = 0; h < 2; h++)
                den[mi][h] += __shfl_xor_sync(0xffffffffu, den[mi][h], o);
    }
    __syncthreads();   // sSum reuse barrier
    if ((lane & 3) == 0) {
        #pragma unroll
        for (int mi = 0; mi < 2; mi++)
            #pragma unroll
            for (int h = 0; h < 2; h++) {
                int row = wm * 32 + mi * 16 + (lane >> 2) + h * 8;
                sSum[wn * 128 + row] = den[mi][h];
            }
    }
    __syncthreads();
    if (tid < 128) {
        float d = sSum[tid] + sSum[128 + tid] + sSum[256 + tid] + sSum[384 + tid];
        float rdv = 1.0f / d;
        sRd[tid] = rdv;
        g_rd[(size_t)bh * S_LEN + (size_t)qt * 128 + tid] = rdv;
    }
    __syncthreads();

    // ---------------- Pass 3: write f32 attn = exp * rd ----------------
    float rd_[2][2];
    #pragma unroll
    for (int mi = 0; mi < 2; mi++)
        #pragma unroll
        for (int h = 0; h < 2; h++)
            rd_[mi][h] = sRd[wm * 32 + mi * 16 + (lane >> 2) + h * 8];

    float* ab = attn + ((size_t)bh * S_LEN + (size_t)qt * 128) * S_LEN;
    for (int t = 0; t < 16; t++) {
        #pragma unroll
        for (int mi = 0; mi < 2; mi++)
            #pragma unroll
            for (int nj = 0; nj < 2; nj++) {
                size_t ad = (fb + (size_t)mi * 128 + t * 8 + wn * 2 + nj) * 32 + lane;
                uint4 H = UH[ad], L = UL[ad];
                float2 e0 = rec2(H.x, L.x);
                float2 e1 = rec2(H.y, L.y);
                float2 e2 = rec2(H.z, L.z);
                float2 e3 = rec2(H.w, L.w);
                float r0 = rd_[mi][0], r1 = rd_[mi][1];
                e0.x *= r0; e0.y *= r0; e2.x *= r0; e2.y *= r0;
                e1.x *= r1; e1.y *= r1; e3.x *= r1; e3.y *= r1;
                int r = wm * 32 + mi * 16 + (lane >> 2);
                int colb = (t * 8 + wn * 2 + nj) * 16 + (lane & 3) * 2;
                *(float2*)(ab + (size_t)r * S_LEN + colb)           = e0;
                *(float2*)(ab + (size_t)(r + 8) * S_LEN + colb)     = e1;
                *(float2*)(ab + (size_t)r * S_LEN + colb + 8)       = e2;
                *(float2*)(ab + (size_t)(r + 8) * S_LEN + colb + 8) = e3;
            }
    }
}

// -------------------------------------------------------------------------
// Kernel 2: out = (exp hi/lo @ V hi/lo) * rd.  A-fragments via direct
// LDG.128 from fragment-native scratch (no smem, no ldmatrix for A).
// V via cp.async + ldmx4t, double-buffered. 256 thr, 8 warps (4m x 2n).
// -------------------------------------------------------------------------
__global__ __launch_bounds__(256) void dsa_av_kernel(float* __restrict__ out)
{
    __shared__ __align__(16) char sm[32768];   // 2 x (VHI 8K | VLO 8K)
    const uint32_t sb = smem_u32(sm);

    const int tid = threadIdx.x, lane = tid & 31, wid = tid >> 5;
    const int bh = blockIdx.y, qt = blockIdx.x;
    const int wm = wid >> 1, wn = wid & 1;

    const __nv_bfloat16* Vh = g_vhi + (size_t)bh * S_LEN * D_DIM;
    const __nv_bfloat16* Vl = g_vlo + (size_t)bh * S_LEN * D_DIM;
    const uint4* UH = (const uint4*)g_shi;
    const uint4* UL = (const uint4*)g_slo;
    const size_t fb = ((size_t)bh * 128 + (size_t)qt * 8 + wm * 2) * 128;

    const int vkr_off = ((lane >> 3) & 1) * 8 + (lane & 7);
    const int vnc_off = lane >> 4;

    auto loadV = [&](int t, int buf) {
        uint32_t bp = sb + (uint32_t)buf * 16384;
        #pragma unroll
        for (int i = 0; i < 2; i++) {
            int idx = tid + i * 256;
            int r = idx >> 3, ch = idx & 7;
            uint32_t o = toff(r, ch);
            cpa16(bp + o,        Vh + ((size_t)t * 64 + r) * 64 + ch * 8);
            cpa16(bp + 8192 + o, Vl + ((size_t)t * 64 + r) * 64 + ch * 8);
        }
    };

    loadV(0, 0); cpa_commit();
    loadV(1, 1); cpa_commit();

    // A fragment register double-buffer
    uint4 cH[2], cL[2], nH[2], nL[2];
    #pragma unroll
    for (int mi = 0; mi < 2; mi++) {
        size_t ad = (fb + (size_t)mi * 128) * 32 + lane;   // t=0, ks=0
        cH[mi] = UH[ad]; cL[mi] = UL[ad];
    }

    cpa_wait<1>();
    __syncthreads();

    float acc[2][4][4] = {};

    for (int t = 0; t < 32; t++) {
        const uint32_t bp = sb + (uint32_t)(t & 1) * 16384;

        #pragma unroll
        for (int ks = 0; ks < 4; ks++) {
            // prefetch next A frags
            if (!(t == 31 && ks == 3)) {
                int nt = (ks == 3) ? t + 1 : t;
                int nks = (ks + 1) & 3;
                #pragma unroll
                for (int mi = 0; mi < 2; mi++) {
                    size_t ad = (fb + (size_t)mi * 128 + nt * 4 + nks) * 32 + lane;
                    nH[mi] = UH[ad]; nL[mi] = UL[ad];
                }
            }
            // V fragments
            uint32_t vh_[2][4], vl_[2][4];
            #pragma unroll
            for (int nj = 0; nj < 2; nj++) {
                int krow = ks * 16 + vkr_off;
                int nc = wn * 4 + nj * 2 + vnc_off;
                uint32_t o = toff(krow, nc);
                ldmx4t(vh_[nj], bp + o);
                ldmx4t(vl_[nj], bp + 8192 + o);
            }
            // term-major mma
            #pragma unroll
            for (int mi = 0; mi < 2; mi++) {
                const uint32_t* ahp = (const uint32_t*)&cH[mi];
                #pragma unroll
                for (int nj = 0; nj < 2; nj++) {
                    mma_bf16(acc[mi][2*nj],   ahp, vh_[nj]);
                    mma_bf16(acc[mi][2*nj+1], ahp, vh_[nj] + 2);
                }
            }
            #pragma unroll
            for (int mi = 0; mi < 2; mi++) {
                const uint32_t* ahp = (const uint32_t*)&cH[mi];
                #pragma unroll
                for (int nj = 0; nj < 2; nj++) {
                    mma_bf16(acc[mi][2*nj],   ahp, vl_[nj]);
                    mma_bf16(acc[mi][2*nj+1], ahp, vl_[nj] + 2);
                }
            }
            #pragma unroll
            for (int mi = 0; mi < 2; mi++) {
                const uint32_t* alp = (const uint32_t*)&cL[mi];
                #pragma unroll
                for (int nj = 0; nj < 2; nj++) {
                    mma_bf16(acc[mi][2*nj],   alp, vh_[nj]);
                    mma_bf16(acc[mi][2*nj+1], alp, vh_[nj] + 2);
                }
            }
            #pragma unroll
            for (int mi = 0; mi < 2; mi++) { cH[mi] = nH[mi]; cL[mi] = nL[mi]; }
        }
        __syncthreads();

        if (t + 2 < 32) {
            loadV(t + 2, t & 1);
            cpa_commit();
        }
        if (t + 1 < 32) {
            if (t + 2 < 32) { cpa_wait<1>(); } else { cpa_wait<0>(); }
            __syncthreads();
        }
    }

    // epilogue: scale by rd and store
    const float* rdp = g_rd + (size_t)bh * S_LEN + (size_t)qt * 128;
    const int qr = lane >> 2, qc = (lane & 3) * 2;
    float* Ob = out + ((size_t)bh * S_LEN + (size_t)qt * 128) * D_DIM;
    #pragma unroll
    for (int mi = 0; mi < 2; mi++) {
        float r0 = rdp[wm * 32 + mi * 16 + qr];
        float r1 = rdp[wm * 32 + mi * 16 + qr + 8];
        #pragma unroll
        for (int ni = 0; ni < 4; ni++) {
            int row = wm * 32 + mi * 16 + qr;
            int col = wn * 32 + ni * 8 + qc;
            float2 v0 = make_float2(acc[mi][ni][0] * r0, acc[mi][ni][1] * r0);
            float2 v1 = make_float2(acc[mi][ni][2] * r1, acc[mi][ni][3] * r1);
            *(float2*)(Ob + (size_t)row * D_DIM + col) = v0;
            *(float2*)(Ob + (size_t)(row + 8) * D_DIM + col) = v1;
        }
    }
}

// -------------------------------------------------------------------------
extern "C" void kernel_launch(void* const* d_in, const int* in_sizes, int n_in,
                              void* d_out, int out_size)
{
    const float* q = (const float*)d_in[0];
    const float* k = (const float*)d_in[1];
    const float* v = (const float*)d_in[2];

    float* outp = (float*)d_out;                                   // BH*S*D
    float* attn = outp + (size_t)BH * S_LEN * D_DIM;               // BH*S*S
    float* tau  = attn + SELEM;                                    // BH*S

    cudaFuncSetAttribute(dsa_fused,
                         cudaFuncAttributeMaxDynamicSharedMemorySize, FS_SMEM);

    dsa_prep<<<2048, 256>>>(q, k, v);
    dsa_fused<<<dim3(S_LEN / 128, BH), 512, FS_SMEM>>>(attn, tau);
    dsa_av_kernel<<<dim3(S_LEN / 128, BH), 256>>>(outp);
}

// round 14
// speedup vs baseline: 1.6946x; 1.6946x over previous
#include <cuda_runtime.h>
#include <cuda_bf16.h>
#include <cstdint>

// DynamicSparseAttention: B=4,H=16,S=2048,D=64
// d_out layout (f32): [out: BH*S*D][attn: BH*S*S][tau: BH*S]
#define S_LEN 2048
#define D_DIM 64
#define BH    64
#define NELEM (BH * S_LEN * D_DIM)                 // 8388608
#define SELEM ((size_t)BH * S_LEN * S_LEN)         // 268435456

// pre-split bf16 hi/lo scratch for Q/K; f32 transposed V
__device__ __align__(16) __nv_bfloat16 g_qhi[NELEM];
__device__ __align__(16) __nv_bfloat16 g_qlo[NELEM];
__device__ __align__(16) __nv_bfloat16 g_khi[NELEM];
__device__ __align__(16) __nv_bfloat16 g_klo[NELEM];
__device__ __align__(16) float g_vt[NELEM];        // [bh][n=64][k=2048]

// ---------------------------------------------------------------- helpers
__device__ __forceinline__ uint32_t smem_u32(const void* p) {
    uint32_t a;
    asm("{ .reg .u64 t; cvta.to.shared.u64 t, %1; cvt.u32.u64 %0, t; }"
        : "=r"(a) : "l"(p));
    return a;
}

// 128B-row tile, 16B-chunk XOR swizzle
__device__ __forceinline__ uint32_t toff(int r, int ch) {
    return (uint32_t)(r * 128 + ((ch ^ (r & 7)) << 4));
}

__device__ __forceinline__ void ldmx4(uint32_t* r, uint32_t a) {
    asm volatile("ldmatrix.sync.aligned.m8n8.x4.shared.b16 {%0,%1,%2,%3}, [%4];"
        : "=r"(r[0]), "=r"(r[1]), "=r"(r[2]), "=r"(r[3]) : "r"(a));
}
__device__ __forceinline__ void mma_bf16(float* c, const uint32_t* a, const uint32_t* b) {
    asm volatile(
        "mma.sync.aligned.m16n8k16.row.col.f32.bf16.bf16.f32 "
        "{%0,%1,%2,%3}, {%4,%5,%6,%7}, {%8,%9}, {%0,%1,%2,%3};"
        : "+f"(c[0]), "+f"(c[1]), "+f"(c[2]), "+f"(c[3])
        : "r"(a[0]), "r"(a[1]), "r"(a[2]), "r"(a[3]), "r"(b[0]), "r"(b[1]));
}
__device__ __forceinline__ uint32_t cvt_tf32(float f) {
    uint32_t u;
    asm("cvt.rna.tf32.f32 %0, %1;" : "=r"(u) : "f"(f));
    return u;
}
__device__ __forceinline__ void mma_tf32(float* c, const uint32_t* a,
                                         uint32_t b0, uint32_t b1) {
    asm volatile(
        "mma.sync.aligned.m16n8k8.row.col.f32.tf32.tf32.f32 "
        "{%0,%1,%2,%3}, {%4,%5,%6,%7}, {%8,%9}, {%0,%1,%2,%3};"
        : "+f"(c[0]), "+f"(c[1]), "+f"(c[2]), "+f"(c[3])
        : "r"(a[0]), "r"(a[1]), "r"(a[2]), "r"(a[3]), "r"(b0), "r"(b1));
}

__device__ __forceinline__ void cpa16(uint32_t dst, const void* src) {
    asm volatile("cp.async.cg.shared.global [%0], [%1], 16;"
                 :: "r"(dst), "l"(__cvta_generic_to_global(src)));
}
__device__ __forceinline__ void cpa_commit() {
    asm volatile("cp.async.commit_group;");
}
template <int N>
__device__ __forceinline__ void cpa_wait() {
    asm volatile("cp.async.wait_group %0;" :: "n"(N));
}

__device__ __forceinline__ uint32_t bfpair(float a, float b) {
    __nv_bfloat162 t;
    t.x = __float2bfloat16(a);
    t.y = __float2bfloat16(b);
    return *reinterpret_cast<uint32_t*>(&t);
}
__device__ __forceinline__ void split2(float a, float b, uint32_t& h, uint32_t& l) {
    __nv_bfloat16 ha = __float2bfloat16(a), hb = __float2bfloat16(b);
    __nv_bfloat162 hp; hp.x = ha; hp.y = hb;
    h = *reinterpret_cast<uint32_t*>(&hp);
    l = bfpair(a - __bfloat162float(ha), b - __bfloat162float(hb));
}
__device__ __forceinline__ void split4(float4 f, uint2& hi, uint2& lo) {
    split2(f.x, f.y, hi.x, lo.x);
    split2(f.z, f.w, hi.y, lo.y);
}

// -------------------------------------------------------------------------
// Kernel 0: pre-split Q*0.125, K into bf16 hi/lo; transpose V -> g_vt f32.
// -------------------------------------------------------------------------
__global__ __launch_bounds__(256) void dsa_prep(
    const float* __restrict__ q, const float* __restrict__ k,
    const float* __restrict__ v)
{
    const int stride = gridDim.x * 256;
    const float4* q4 = (const float4*)q;
    const float4* k4 = (const float4*)k;
    const float4* v4 = (const float4*)v;
    uint2* qh = (uint2*)g_qhi; uint2* ql = (uint2*)g_qlo;
    uint2* kh = (uint2*)g_khi; uint2* kl = (uint2*)g_klo;

    for (int i = blockIdx.x * 256 + threadIdx.x; i < NELEM / 4; i += stride) {
        float4 fq = q4[i];
        fq.x *= 0.125f; fq.y *= 0.125f; fq.z *= 0.125f; fq.w *= 0.125f;
        uint2 hi, lo;
        split4(fq, hi, lo); qh[i] = hi; ql[i] = lo;
        split4(k4[i], hi, lo); kh[i] = hi; kl[i] = lo;

        // V transpose: i indexes [bh][kk][n4] float4 (16 float4 per row)
        float4 fv = v4[i];
        int bh = i >> 15;                 // / (2048*16)
        int rem = i & 32767;
        int kk = rem >> 4;
        int n4 = rem & 15;
        float* vt = g_vt + ((size_t)bh * 64 + n4 * 4) * S_LEN + kk;
        vt[0]          = fv.x;
        vt[S_LEN]      = fv.y;
        vt[2 * S_LEN]  = fv.z;
        vt[3 * S_LEN]  = fv.w;
    }
}

// -------------------------------------------------------------------------
// Kernel 1: raw scores = (Q*scale) K^T -> f32 attn buffer (pre-softmax).
// CTA = 128-row q-stripe over 16 k-tiles of 128. 512 thr, 16 warps (4m x 4n).
// A frags cached in regs; K tiles via cp.async double-buffered. SMEM 96KB.
// bf16 hi/lo 3-term split (proven 1.4e-5).
// -------------------------------------------------------------------------
#define SC_SMEM 98304
__global__ __launch_bounds__(512) void dsa_scores_kernel(float* __restrict__ attn)
{
    extern __shared__ __align__(16) char sm[];
    const uint32_t sb = smem_u32(sm);
    const uint32_t QHI = 0, QLO = 16384;      // K bufs at 32768 + b*32768

    const int tid = threadIdx.x, lane = tid & 31, wid = tid >> 5;
    const int qt = blockIdx.x, bh = blockIdx.y;

    const __nv_bfloat16* Qh = g_qhi + ((size_t)bh * S_LEN + (size_t)qt * 128) * D_DIM;
    const __nv_bfloat16* Ql = g_qlo + ((size_t)bh * S_LEN + (size_t)qt * 128) * D_DIM;
    const __nv_bfloat16* Kh = g_khi + (size_t)bh * S_LEN * D_DIM;
    const __nv_bfloat16* Kl = g_klo + (size_t)bh * S_LEN * D_DIM;

    // group 0: Q hi/lo + K tile 0
    #pragma unroll
    for (int i = 0; i < 2; i++) {
        int idx = tid + i * 512;
        int r = idx >> 3, ch = idx & 7;
        uint32_t o = toff(r, ch);
        cpa16(sb + QHI + o, Qh + r * 64 + ch * 8);
        cpa16(sb + QLO + o, Ql + r * 64 + ch * 8);
        cpa16(sb + 32768 + o, Kh + r * 64 + ch * 8);
        cpa16(sb + 32768 + 16384 + o, Kl + r * 64 + ch * 8);
    }
    cpa_commit();
    // group 1: K tile 1
    #pragma unroll
    for (int i = 0; i < 2; i++) {
        int idx = tid + i * 512;
        int r = idx >> 3, ch = idx & 7;
        uint32_t o = toff(r, ch);
        cpa16(sb + 65536 + o, Kh + (size_t)(128 + r) * 64 + ch * 8);
        cpa16(sb + 65536 + 16384 + o, Kl + (size_t)(128 + r) * 64 + ch * 8);
    }
    cpa_commit();
    cpa_wait<1>();
    __syncthreads();

    const int wm = wid >> 2, wn = wid & 3;
    const int alr = lane & 7, alm = (lane >> 3) & 1, alk = lane >> 4;
    const int brow_off = ((lane >> 4) << 3) + (lane & 7);
    const int bchk_off = (lane >> 3) & 1;

    // A fragments cached in registers for the whole kernel
    uint32_t ah[4][2][4], al[4][2][4];
    #pragma unroll
    for (int ks = 0; ks < 4; ks++)
        #pragma unroll
        for (int mi = 0; mi < 2; mi++) {
            int row = wm * 32 + mi * 16 + alr + alm * 8;
            uint32_t o = toff(row, ks * 2 + alk);
            ldmx4(ah[ks][mi], sb + QHI + o);
            ldmx4(al[ks][mi], sb + QLO + o);
        }

    const int qr = lane >> 2, qc = (lane & 3) * 2;
    float* abase = attn + ((size_t)bh * S_LEN + (size_t)qt * 128) * S_LEN;

    for (int t = 0; t < 16; t++) {
        const uint32_t KB = sb + 32768 + (uint32_t)(t & 1) * 32768;

        float acc[2][4][4] = {};
        #pragma unroll
        for (int ks = 0; ks < 4; ks++) {
            uint32_t bh_[2][4], bl_[2][4];
            #pragma unroll
            for (int nj = 0; nj < 2; nj++) {
                int row = wn * 32 + nj * 16 + brow_off;
                uint32_t o = toff(row, ks * 2 + bchk_off);
                ldmx4(bh_[nj], KB + o);
                ldmx4(bl_[nj], KB + 16384 + o);
            }
            #pragma unroll
            for (int mi = 0; mi < 2; mi++)
                #pragma unroll
                for (int nj = 0; nj < 2; nj++) {
                    mma_bf16(acc[mi][2*nj],   ah[ks][mi], bh_[nj]);
                    mma_bf16(acc[mi][2*nj+1], ah[ks][mi], bh_[nj] + 2);
                }
            #pragma unroll
            for (int mi = 0; mi < 2; mi++)
                #pragma unroll
                for (int nj = 0; nj < 2; nj++) {
                    mma_bf16(acc[mi][2*nj],   ah[ks][mi], bl_[nj]);
                    mma_bf16(acc[mi][2*nj+1], ah[ks][mi], bl_[nj] + 2);
                }
            #pragma unroll
            for (int mi = 0; mi < 2; mi++)
                #pragma unroll
                for (int nj = 0; nj < 2; nj++) {
                    mma_bf16(acc[mi][2*nj],   al[ks][mi], bh_[nj]);
                    mma_bf16(acc[mi][2*nj+1], al[ks][mi], bh_[nj] + 2);
                }
        }

        float* base = abase + (size_t)t * 128;
        #pragma unroll
        for (int mi = 0; mi < 2; mi++) {
            #pragma unroll
            for (int ni = 0; ni < 4; ni++) {
                int row = wm * 32 + mi * 16 + qr;
                int col = wn * 32 + ni * 8 + qc;
                float2 v0 = make_float2(acc[mi][ni][0], acc[mi][ni][1]);
                float2 v1 = make_float2(acc[mi][ni][2], acc[mi][ni][3]);
                *(float2*)(base + (size_t)row * S_LEN + col) = v0;
                *(float2*)(base + (size_t)(row + 8) * S_LEN + col) = v1;
            }
        }
        __syncthreads();

        if (t + 2 < 16) {
            const __nv_bfloat16* th = Kh + (size_t)(t + 2) * 128 * 64;
            const __nv_bfloat16* tl = Kl + (size_t)(t + 2) * 128 * 64;
            uint32_t dst = sb + 32768 + (uint32_t)(t & 1) * 32768;
            #pragma unroll
            for (int i = 0; i < 2; i++) {
                int idx = tid + i * 512;
                int r = idx >> 3, ch = idx & 7;
                uint32_t o = toff(r, ch);
                cpa16(dst + o, th + r * 64 + ch * 8);
                cpa16(dst + 16384 + o, tl + r * 64 + ch * 8);
            }
            cpa_commit();
            cpa_wait<1>();
        } else {
            cpa_wait<0>();
        }
        __syncthreads();
    }
}

// -------------------------------------------------------------------------
// Kernel 2: per-row variance (ddof=1) -> tau -> softmax(scores/tau) in place.
// Warp-per-row, row in registers. No smem, no block barriers.
// -------------------------------------------------------------------------
__global__ __launch_bounds__(256, 2) void dsa_softvar_kernel(
    float* __restrict__ attn, float* __restrict__ tau_out)
{
    const int lane = threadIdx.x & 31;
    const int w = threadIdx.x >> 5;
    const size_t row = (size_t)blockIdx.x * 8 + w;
    float4* r4 = (float4*)(attn + row * S_LEN);

    float4 d[16];
    float sum = 0.f, sq = 0.f, mx = -3.402823466e38f;
    #pragma unroll
    for (int i = 0; i < 16; i++) {
        float4 f = r4[lane + 32 * i];
        d[i] = f;
        sum += f.x + f.y + f.z + f.w;
        sq = fmaf(f.x, f.x, sq); sq = fmaf(f.y, f.y, sq);
        sq = fmaf(f.z, f.z, sq); sq = fmaf(f.w, f.w, sq);
        mx = fmaxf(mx, fmaxf(fmaxf(f.x, f.y), fmaxf(f.z, f.w)));
    }
    #pragma unroll
    for (int o = 16; o; o >>= 1) {
        sum += __shfl_xor_sync(0xffffffffu, sum, o);
        sq  += __shfl_xor_sync(0xffffffffu, sq, o);
        mx   = fmaxf(mx, __shfl_xor_sync(0xffffffffu, mx, o));
    }

    float mean = sum * (1.0f / S_LEN);
    float var  = (sq - sum * mean) * (1.0f / (S_LEN - 1));  // ddof=1
    float tau  = fmaxf(1.0f / (1.0f + var), 0.3f);          // BASE=1, MIN=0.3
    float itau = 1.0f / tau;
    if (lane == 0) tau_out[row] = tau;

    float ls = 0.f;
    #pragma unroll
    for (int i = 0; i < 16; i++) {
        float4 f = d[i];
        f.x = __expf((f.x - mx) * itau);
        f.y = __expf((f.y - mx) * itau);
        f.z = __expf((f.z - mx) * itau);
        f.w = __expf((f.w - mx) * itau);
        d[i] = f;
        ls += f.x + f.y + f.z + f.w;
    }
    #pragma unroll
    for (int o = 16; o; o >>= 1) ls += __shfl_xor_sync(0xffffffffu, ls, o);
    const float rd = 1.0f / ls;

    #pragma unroll
    for (int i = 0; i < 16; i++) {
        float4 f = d[i];
        f.x *= rd; f.y *= rd; f.z *= rd; f.w *= rd;
        r4[lane + 32 * i] = f;
    }
}

// -------------------------------------------------------------------------
// Kernel 3: out = attn @ V via single-term tf32 mma (m16n8k8).
// attn read as f32 (cp.async, double-buffered), fragments via conflict-free
// scalar LDS + cvt.rna.tf32. V from pre-transposed f32 g_vt [n][k].
// 256 thr, 8 warps (4m x 2n), warp tile 32x32. SMEM 102KB (2 bufs).
// smem layout per buffer: A[128][68] f32 | V[64][68] f32 (stride 68 = no
// bank conflicts: lane -> bank (4*(lane>>2)+(lane&3)) mod 32 = lane).
// -------------------------------------------------------------------------
#define AVT_BUF  52224             // (128*68 + 64*68) * 4 bytes
#define AVT_SMEM 104448

__global__ __launch_bounds__(256) void dsa_av_tf32(
    const float* __restrict__ attn, float* __restrict__ out)
{
    extern __shared__ __align__(16) float smf[];
    const uint32_t sb = smem_u32(smf);

    const int tid = threadIdx.x, lane = tid & 31, wid = tid >> 5;
    const int bh = blockIdx.y, qt = blockIdx.x;
    const int wm = wid >> 1, wn = wid & 1;

    const float* Ab = attn + ((size_t)bh * S_LEN + (size_t)qt * 128) * S_LEN;
    const float* Vt = g_vt + (size_t)bh * 64 * S_LEN;

    auto load_chunk = [&](int t, int buf) {
        uint32_t bp = sb + (uint32_t)buf * AVT_BUF;
        const int kk = t * 64;
        #pragma unroll
        for (int i = 0; i < 8; i++) {              // A: 128 x 64 f32
            int idx = tid + i * 256;
            int r = idx >> 4, seg = idx & 15;
            cpa16(bp + (uint32_t)(r * 272 + seg * 16),
                  Ab + (size_t)r * S_LEN + kk + seg * 4);
        }
        #pragma unroll
        for (int i = 0; i < 4; i++) {              // V^T: 64 x 64 f32
            int idx = tid + i * 256;
            int n = idx >> 4, seg = idx & 15;
            cpa16(bp + (uint32_t)(128 * 272 + n * 272 + seg * 16),
                  Vt + (size_t)n * S_LEN + kk + seg * 4);
        }
    };

    load_chunk(0, 0); cpa_commit();
    load_chunk(1, 1); cpa_commit();
    cpa_wait<1>();
    __syncthreads();

    float acc[2][4][4] = {};
    const int ar = lane >> 2, ac = lane & 3;

    for (int t = 0; t < 32; t++) {
        const float* A0 = smf + (size_t)(t & 1) * (AVT_BUF / 4);
        const float* V0 = A0 + 128 * 68;

        #pragma unroll
        for (int s = 0; s < 8; s++) {
            // A tf32 fragments: a0=(r,c) a1=(r+8,c) a2=(r,c+4) a3=(r+8,c+4)
            uint32_t av[2][4];
            #pragma unroll
            for (int mi = 0; mi < 2; mi++) {
                int r = wm * 32 + mi * 16 + ar;
                int c = s * 8 + ac;
                av[mi][0] = cvt_tf32(A0[r * 68 + c]);
                av[mi][1] = cvt_tf32(A0[(r + 8) * 68 + c]);
                av[mi][2] = cvt_tf32(A0[r * 68 + c + 4]);
                av[mi][3] = cvt_tf32(A0[(r + 8) * 68 + c + 4]);
            }
            // B tf32 fragments: b0=(k,n) b1=(k+4,n); V0 is [n][k]
            #pragma unroll
            for (int nj = 0; nj < 4; nj++) {
                int n = wn * 32 + nj * 8 + ar;
                int k = s * 8 + ac;
                uint32_t b0 = cvt_tf32(V0[n * 68 + k]);
                uint32_t b1 = cvt_tf32(V0[n * 68 + k + 4]);
                mma_tf32(acc[0][nj], av[0], b0, b1);
                mma_tf32(acc[1][nj], av[1], b0, b1);
            }
        }
        __syncthreads();

        if (t + 2 < 32) {
            load_chunk(t + 2, t & 1);
            cpa_commit();
        }
        if (t + 1 < 32) {
            if (t + 2 < 32) { cpa_wait<1>(); } else { cpa_wait<0>(); }
            __syncthreads();
        }
    }

    const int qr = lane >> 2, qc = (lane & 3) * 2;
    float* Ob = out + ((size_t)bh * S_LEN + (size_t)qt * 128) * D_DIM;
    #pragma unroll
    for (int mi = 0; mi < 2; mi++) {
        #pragma unroll
        for (int nj = 0; nj < 4; nj++) {
            int row = wm * 32 + mi * 16 + qr;
            int col = wn * 32 + nj * 8 + qc;
            float2 v0 = make_float2(acc[mi][nj][0], acc[mi][nj][1]);
            float2 v1 = make_float2(acc[mi][nj][2], acc[mi][nj][3]);
            *(float2*)(Ob + (size_t)row * D_DIM + col) = v0;
            *(float2*)(Ob + (size_t)(row + 8) * D_DIM + col) = v1;
        }
    }
}

// -------------------------------------------------------------------------
extern "C" void kernel_launch(void* const* d_in, const int* in_sizes, int n_in,
                              void* d_out, int out_size)
{
    const float* q = (const float*)d_in[0];
    const float* k = (const float*)d_in[1];
    const float* v = (const float*)d_in[2];

    float* outp = (float*)d_out;                                   // BH*S*D
    float* attn = outp + (size_t)BH * S_LEN * D_DIM;               // BH*S*S
    float* tau  = attn + SELEM;                                    // BH*S

    cudaFuncSetAttribute(dsa_scores_kernel,
                         cudaFuncAttributeMaxDynamicSharedMemorySize, SC_SMEM);
    cudaFuncSetAttribute(dsa_av_tf32,
                         cudaFuncAttributeMaxDynamicSharedMemorySize, AVT_SMEM);

    dsa_prep<<<2048, 256>>>(q, k, v);
    dsa_scores_kernel<<<dim3(S_LEN / 128, BH), 512, SC_SMEM>>>(attn);
    dsa_softvar_kernel<<<BH * S_LEN / 8, 256>>>(attn, tau);
    dsa_av_tf32<<<dim3(S_LEN / 128, BH), 256, AVT_SMEM>>>(attn, outp);
}

// round 15
// speedup vs baseline: 1.7466x; 1.0307x over previous
#include <cuda_runtime.h>
#include <cuda_bf16.h>
#include <cstdint>

// DynamicSparseAttention: B=4,H=16,S=2048,D=64
// d_out layout (f32): [out: BH*S*D][attn: BH*S*S][tau: BH*S]
#define S_LEN 2048
#define D_DIM 64
#define BH    64
#define NELEM (BH * S_LEN * D_DIM)                 // 8388608
#define SELEM ((size_t)BH * S_LEN * S_LEN)         // 268435456

// pre-split bf16 hi/lo scratch for Q/K; f32(tf32-rounded) transposed V
__device__ __align__(16) __nv_bfloat16 g_qhi[NELEM];
__device__ __align__(16) __nv_bfloat16 g_qlo[NELEM];
__device__ __align__(16) __nv_bfloat16 g_khi[NELEM];
__device__ __align__(16) __nv_bfloat16 g_klo[NELEM];
__device__ __align__(16) float g_vt[NELEM];        // [bh][n=64][k=2048]

// ---------------------------------------------------------------- helpers
__device__ __forceinline__ uint32_t smem_u32(const void* p) {
    uint32_t a;
    asm("{ .reg .u64 t; cvta.to.shared.u64 t, %1; cvt.u32.u64 %0, t; }"
        : "=r"(a) : "l"(p));
    return a;
}

// 128B-row tile, 16B-chunk XOR swizzle
__device__ __forceinline__ uint32_t toff(int r, int ch) {
    return (uint32_t)(r * 128 + ((ch ^ (r & 7)) << 4));
}

__device__ __forceinline__ void ldmx4(uint32_t* r, uint32_t a) {
    asm volatile("ldmatrix.sync.aligned.m8n8.x4.shared.b16 {%0,%1,%2,%3}, [%4];"
        : "=r"(r[0]), "=r"(r[1]), "=r"(r[2]), "=r"(r[3]) : "r"(a));
}
__device__ __forceinline__ void mma_bf16(float* c, const uint32_t* a, const uint32_t* b) {
    asm volatile(
        "mma.sync.aligned.m16n8k16.row.col.f32.bf16.bf16.f32 "
        "{%0,%1,%2,%3}, {%4,%5,%6,%7}, {%8,%9}, {%0,%1,%2,%3};"
        : "+f"(c[0]), "+f"(c[1]), "+f"(c[2]), "+f"(c[3])
        : "r"(a[0]), "r"(a[1]), "r"(a[2]), "r"(a[3]), "r"(b[0]), "r"(b[1]));
}
__device__ __forceinline__ uint32_t cvt_tf32(float f) {
    uint32_t u;
    asm("cvt.rna.tf32.f32 %0, %1;" : "=r"(u) : "f"(f));
    return u;
}
__device__ __forceinline__ float round_tf32(float f) {
    return __uint_as_float(cvt_tf32(f));
}
__device__ __forceinline__ void mma_tf32(float* c, const uint32_t* a,
                                         uint32_t b0, uint32_t b1) {
    asm volatile(
        "mma.sync.aligned.m16n8k8.row.col.f32.tf32.tf32.f32 "
        "{%0,%1,%2,%3}, {%4,%5,%6,%7}, {%8,%9}, {%0,%1,%2,%3};"
        : "+f"(c[0]), "+f"(c[1]), "+f"(c[2]), "+f"(c[3])
        : "r"(a[0]), "r"(a[1]), "r"(a[2]), "r"(a[3]), "r"(b0), "r"(b1));
}

__device__ __forceinline__ void cpa16(uint32_t dst, const void* src) {
    asm volatile("cp.async.cg.shared.global [%0], [%1], 16;"
                 :: "r"(dst), "l"(__cvta_generic_to_global(src)));
}
__device__ __forceinline__ void cpa_commit() {
    asm volatile("cp.async.commit_group;");
}
template <int N>
__device__ __forceinline__ void cpa_wait() {
    asm volatile("cp.async.wait_group %0;" :: "n"(N));
}

__device__ __forceinline__ uint32_t bfpair(float a, float b) {
    __nv_bfloat162 t;
    t.x = __float2bfloat16(a);
    t.y = __float2bfloat16(b);
    return *reinterpret_cast<uint32_t*>(&t);
}
__device__ __forceinline__ void split2(float a, float b, uint32_t& h, uint32_t& l) {
    __nv_bfloat16 ha = __float2bfloat16(a), hb = __float2bfloat16(b);
    __nv_bfloat162 hp; hp.x = ha; hp.y = hb;
    h = *reinterpret_cast<uint32_t*>(&hp);
    l = bfpair(a - __bfloat162float(ha), b - __bfloat162float(hb));
}
__device__ __forceinline__ void split4(float4 f, uint2& hi, uint2& lo) {
    split2(f.x, f.y, hi.x, lo.x);
    split2(f.z, f.w, hi.y, lo.y);
}

// -------------------------------------------------------------------------
// Kernel 0: pre-split Q*0.125, K into bf16 hi/lo; transpose V -> g_vt
// (tf32-rounded, so AV needs no cvt).
// -------------------------------------------------------------------------
__global__ __launch_bounds__(256) void dsa_prep(
    const float* __restrict__ q, const float* __restrict__ k,
    const float* __restrict__ v)
{
    const int stride = gridDim.x * 256;
    const float4* q4 = (const float4*)q;
    const float4* k4 = (const float4*)k;
    const float4* v4 = (const float4*)v;
    uint2* qh = (uint2*)g_qhi; uint2* ql = (uint2*)g_qlo;
    uint2* kh = (uint2*)g_khi; uint2* kl = (uint2*)g_klo;

    for (int i = blockIdx.x * 256 + threadIdx.x; i < NELEM / 4; i += stride) {
        float4 fq = q4[i];
        fq.x *= 0.125f; fq.y *= 0.125f; fq.z *= 0.125f; fq.w *= 0.125f;
        uint2 hi, lo;
        split4(fq, hi, lo); qh[i] = hi; ql[i] = lo;
        split4(k4[i], hi, lo); kh[i] = hi; kl[i] = lo;

        // V transpose + tf32 rounding: i indexes [bh][kk][n4] float4
        float4 fv = v4[i];
        int bh = i >> 15;                 // / (2048*16)
        int rem = i & 32767;
        int kk = rem >> 4;
        int n4 = rem & 15;
        float* vt = g_vt + ((size_t)bh * 64 + n4 * 4) * S_LEN + kk;
        vt[0]          = round_tf32(fv.x);
        vt[S_LEN]      = round_tf32(fv.y);
        vt[2 * S_LEN]  = round_tf32(fv.z);
        vt[3 * S_LEN]  = round_tf32(fv.w);
    }
}

// -------------------------------------------------------------------------
// Kernel 1: raw scores = (Q*scale) K^T -> f32 attn buffer (pre-softmax).
// CTA = 128-row q-stripe over 16 k-tiles of 128. 512 thr, 16 warps (4m x 4n).
// A frags cached in regs; K tiles via cp.async double-buffered. SMEM 96KB.
// bf16 hi/lo 3-term split. Streaming stores (.cs) — read once much later.
// -------------------------------------------------------------------------
#define SC_SMEM 98304
__global__ __launch_bounds__(512) void dsa_scores_kernel(float* __restrict__ attn)
{
    extern __shared__ __align__(16) char sm[];
    const uint32_t sb = smem_u32(sm);
    const uint32_t QHI = 0, QLO = 16384;      // K bufs at 32768 + b*32768

    const int tid = threadIdx.x, lane = tid & 31, wid = tid >> 5;
    const int qt = blockIdx.x, bh = blockIdx.y;

    const __nv_bfloat16* Qh = g_qhi + ((size_t)bh * S_LEN + (size_t)qt * 128) * D_DIM;
    const __nv_bfloat16* Ql = g_qlo + ((size_t)bh * S_LEN + (size_t)qt * 128) * D_DIM;
    const __nv_bfloat16* Kh = g_khi + (size_t)bh * S_LEN * D_DIM;
    const __nv_bfloat16* Kl = g_klo + (size_t)bh * S_LEN * D_DIM;

    // group 0: Q hi/lo + K tile 0
    #pragma unroll
    for (int i = 0; i < 2; i++) {
        int idx = tid + i * 512;
        int r = idx >> 3, ch = idx & 7;
        uint32_t o = toff(r, ch);
        cpa16(sb + QHI + o, Qh + r * 64 + ch * 8);
        cpa16(sb + QLO + o, Ql + r * 64 + ch * 8);
        cpa16(sb + 32768 + o, Kh + r * 64 + ch * 8);
        cpa16(sb + 32768 + 16384 + o, Kl + r * 64 + ch * 8);
    }
    cpa_commit();
    // group 1: K tile 1
    #pragma unroll
    for (int i = 0; i < 2; i++) {
        int idx = tid + i * 512;
        int r = idx >> 3, ch = idx & 7;
        uint32_t o = toff(r, ch);
        cpa16(sb + 65536 + o, Kh + (size_t)(128 + r) * 64 + ch * 8);
        cpa16(sb + 65536 + 16384 + o, Kl + (size_t)(128 + r) * 64 + ch * 8);
    }
    cpa_commit();
    cpa_wait<1>();
    __syncthreads();

    const int wm = wid >> 2, wn = wid & 3;
    const int alr = lane & 7, alm = (lane >> 3) & 1, alk = lane >> 4;
    const int brow_off = ((lane >> 4) << 3) + (lane & 7);
    const int bchk_off = (lane >> 3) & 1;

    // A fragments cached in registers for the whole kernel
    uint32_t ah[4][2][4], al[4][2][4];
    #pragma unroll
    for (int ks = 0; ks < 4; ks++)
        #pragma unroll
        for (int mi = 0; mi < 2; mi++) {
            int row = wm * 32 + mi * 16 + alr + alm * 8;
            uint32_t o = toff(row, ks * 2 + alk);
            ldmx4(ah[ks][mi], sb + QHI + o);
            ldmx4(al[ks][mi], sb + QLO + o);
        }

    const int qr = lane >> 2, qc = (lane & 3) * 2;
    float* abase = attn + ((size_t)bh * S_LEN + (size_t)qt * 128) * S_LEN;

    for (int t = 0; t < 16; t++) {
        const uint32_t KB = sb + 32768 + (uint32_t)(t & 1) * 32768;

        float acc[2][4][4] = {};
        #pragma unroll
        for (int ks = 0; ks < 4; ks++) {
            uint32_t bh_[2][4], bl_[2][4];
            #pragma unroll
            for (int nj = 0; nj < 2; nj++) {
                int row = wn * 32 + nj * 16 + brow_off;
                uint32_t o = toff(row, ks * 2 + bchk_off);
                ldmx4(bh_[nj], KB + o);
                ldmx4(bl_[nj], KB + 16384 + o);
            }
            #pragma unroll
            for (int mi = 0; mi < 2; mi++)
                #pragma unroll
                for (int nj = 0; nj < 2; nj++) {
                    mma_bf16(acc[mi][2*nj],   ah[ks][mi], bh_[nj]);
                    mma_bf16(acc[mi][2*nj+1], ah[ks][mi], bh_[nj] + 2);
                }
            #pragma unroll
            for (int mi = 0; mi < 2; mi++)
                #pragma unroll
                for (int nj = 0; nj < 2; nj++) {
                    mma_bf16(acc[mi][2*nj],   ah[ks][mi], bl_[nj]);
                    mma_bf16(acc[mi][2*nj+1], ah[ks][mi], bl_[nj] + 2);
                }
            #pragma unroll
            for (int mi = 0; mi < 2; mi++)
                #pragma unroll
                for (int nj = 0; nj < 2; nj++) {
                    mma_bf16(acc[mi][2*nj],   al[ks][mi], bh_[nj]);
                    mma_bf16(acc[mi][2*nj+1], al[ks][mi], bh_[nj] + 2);
                }
        }

        float* base = abase + (size_t)t * 128;
        #pragma unroll
        for (int mi = 0; mi < 2; mi++) {
            #pragma unroll
            for (int ni = 0; ni < 4; ni++) {
                int row = wm * 32 + mi * 16 + qr;
                int col = wn * 32 + ni * 8 + qc;
                float2 v0 = make_float2(acc[mi][ni][0], acc[mi][ni][1]);
                float2 v1 = make_float2(acc[mi][ni][2], acc[mi][ni][3]);
                __stcs((float2*)(base + (size_t)row * S_LEN + col), v0);
                __stcs((float2*)(base + (size_t)(row + 8) * S_LEN + col), v1);
            }
        }
        __syncthreads();

        if (t + 2 < 16) {
            const __nv_bfloat16* th = Kh + (size_t)(t + 2) * 128 * 64;
            const __nv_bfloat16* tl = Kl + (size_t)(t + 2) * 128 * 64;
            uint32_t dst = sb + 32768 + (uint32_t)(t & 1) * 32768;
            #pragma unroll
            for (int i = 0; i < 2; i++) {
                int idx = tid + i * 512;
                int r = idx >> 3, ch = idx & 7;
                uint32_t o = toff(r, ch);
                cpa16(dst + o, th + r * 64 + ch * 8);
                cpa16(dst + 16384 + o, tl + r * 64 + ch * 8);
            }
            cpa_commit();
            cpa_wait<1>();
        } else {
            cpa_wait<0>();
        }
        __syncthreads();
    }
}

// -------------------------------------------------------------------------
// Kernel 2: per-row variance (ddof=1) -> tau -> softmax(scores/tau) in place.
// Warp-per-row, row in registers. Output values tf32-ROUNDED (still valid
// f32; lets AV consume raw bits with zero cvt). Streaming ld/st hints.
// -------------------------------------------------------------------------
__global__ __launch_bounds__(256, 2) void dsa_softvar_kernel(
    float* __restrict__ attn, float* __restrict__ tau_out)
{
    const int lane = threadIdx.x & 31;
    const int w = threadIdx.x >> 5;
    const size_t row = (size_t)blockIdx.x * 8 + w;
    float4* r4 = (float4*)(attn + row * S_LEN);

    float4 d[16];
    float sum = 0.f, sq = 0.f, mx = -3.402823466e38f;
    #pragma unroll
    for (int i = 0; i < 16; i++) {
        float4 f = __ldcs(&r4[lane + 32 * i]);
        d[i] = f;
        sum += f.x + f.y + f.z + f.w;
        sq = fmaf(f.x, f.x, sq); sq = fmaf(f.y, f.y, sq);
        sq = fmaf(f.z, f.z, sq); sq = fmaf(f.w, f.w, sq);
        mx = fmaxf(mx, fmaxf(fmaxf(f.x, f.y), fmaxf(f.z, f.w)));
    }
    #pragma unroll
    for (int o = 16; o; o >>= 1) {
        sum += __shfl_xor_sync(0xffffffffu, sum, o);
        sq  += __shfl_xor_sync(0xffffffffu, sq, o);
        mx   = fmaxf(mx, __shfl_xor_sync(0xffffffffu, mx, o));
    }

    float mean = sum * (1.0f / S_LEN);
    float var  = (sq - sum * mean) * (1.0f / (S_LEN - 1));  // ddof=1
    float tau  = fmaxf(1.0f / (1.0f + var), 0.3f);          // BASE=1, MIN=0.3
    float itau = 1.0f / tau;
    if (lane == 0) tau_out[row] = tau;

    float ls = 0.f;
    #pragma unroll
    for (int i = 0; i < 16; i++) {
        float4 f = d[i];
        f.x = __expf((f.x - mx) * itau);
        f.y = __expf((f.y - mx) * itau);
        f.z = __expf((f.z - mx) * itau);
        f.w = __expf((f.w - mx) * itau);
        d[i] = f;
        ls += f.x + f.y + f.z + f.w;
    }
    #pragma unroll
    for (int o = 16; o; o >>= 1) ls += __shfl_xor_sync(0xffffffffu, ls, o);
    const float rd = 1.0f / ls;

    #pragma unroll
    for (int i = 0; i < 16; i++) {
        float4 f = d[i];
        f.x = round_tf32(f.x * rd);
        f.y = round_tf32(f.y * rd);
        f.z = round_tf32(f.z * rd);
        f.w = round_tf32(f.w * rd);
        __stcs(&r4[lane + 32 * i], f);
    }
}

// -------------------------------------------------------------------------
// Kernel 3: out = attn @ V via single-term tf32 mma (m16n8k8).
// attn and V^T are PRE-ROUNDED to tf32 -> raw f32 bits are valid operands:
// zero cvt in the hot loop. cp.async double-buffered, conflict-free LDS.
// 256 thr, 8 warps (4m x 2n), warp tile 32x32. SMEM 102KB (2 bufs).
// -------------------------------------------------------------------------
#define AVT_BUF  52224             // (128*68 + 64*68) * 4 bytes
#define AVT_SMEM 104448

__global__ __launch_bounds__(256) void dsa_av_tf32(
    const float* __restrict__ attn, float* __restrict__ out)
{
    extern __shared__ __align__(16) float smf[];
    const uint32_t sb = smem_u32(smf);

    const int tid = threadIdx.x, lane = tid & 31, wid = tid >> 5;
    const int bh = blockIdx.y, qt = blockIdx.x;
    const int wm = wid >> 1, wn = wid & 1;

    const float* Ab = attn + ((size_t)bh * S_LEN + (size_t)qt * 128) * S_LEN;
    const float* Vt = g_vt + (size_t)bh * 64 * S_LEN;

    auto load_chunk = [&](int t, int buf) {
        uint32_t bp = sb + (uint32_t)buf * AVT_BUF;
        const int kk = t * 64;
        #pragma unroll
        for (int i = 0; i < 8; i++) {              // A: 128 x 64 f32
            int idx = tid + i * 256;
            int r = idx >> 4, seg = idx & 15;
            cpa16(bp + (uint32_t)(r * 272 + seg * 16),
                  Ab + (size_t)r * S_LEN + kk + seg * 4);
        }
        #pragma unroll
        for (int i = 0; i < 4; i++) {              // V^T: 64 x 64 f32
            int idx = tid + i * 256;
            int n = idx >> 4, seg = idx & 15;
            cpa16(bp + (uint32_t)(128 * 272 + n * 272 + seg * 16),
                  Vt + (size_t)n * S_LEN + kk + seg * 4);
        }
    };

    load_chunk(0, 0); cpa_commit();
    load_chunk(1, 1); cpa_commit();
    cpa_wait<1>();
    __syncthreads();

    float acc[2][4][4] = {};
    const int ar = lane >> 2, ac = lane & 3;

    for (int t = 0; t < 32; t++) {
        const float* A0 = smf + (size_t)(t & 1) * (AVT_BUF / 4);
        const float* V0 = A0 + 128 * 68;

        #pragma unroll
        for (int s = 0; s < 8; s++) {
            // A tf32 fragments (raw bits; values pre-rounded to tf32)
            uint32_t av[2][4];
            #pragma unroll
            for (int mi = 0; mi < 2; mi++) {
                int r = wm * 32 + mi * 16 + ar;
                int c = s * 8 + ac;
                av[mi][0] = __float_as_uint(A0[r * 68 + c]);
                av[mi][1] = __float_as_uint(A0[(r + 8) * 68 + c]);
                av[mi][2] = __float_as_uint(A0[r * 68 + c + 4]);
                av[mi][3] = __float_as_uint(A0[(r + 8) * 68 + c + 4]);
            }
            // B tf32 fragments; V0 is [n][k], also pre-rounded
            #pragma unroll
            for (int nj = 0; nj < 4; nj++) {
                int n = wn * 32 + nj * 8 + ar;
                int k = s * 8 + ac;
                uint32_t b0 = __float_as_uint(V0[n * 68 + k]);
                uint32_t b1 = __float_as_uint(V0[n * 68 + k + 4]);
                mma_tf32(acc[0][nj], av[0], b0, b1);
                mma_tf32(acc[1][nj], av[1], b0, b1);
            }
        }
        __syncthreads();

        if (t + 2 < 32) {
            load_chunk(t + 2, t & 1);
            cpa_commit();
        }
        if (t + 1 < 32) {
            if (t + 2 < 32) { cpa_wait<1>(); } else { cpa_wait<0>(); }
            __syncthreads();
        }
    }

    const int qr = lane >> 2, qc = (lane & 3) * 2;
    float* Ob = out + ((size_t)bh * S_LEN + (size_t)qt * 128) * D_DIM;
    #pragma unroll
    for (int mi = 0; mi < 2; mi++) {
        #pragma unroll
        for (int nj = 0; nj < 4; nj++) {
            int row = wm * 32 + mi * 16 + qr;
            int col = wn * 32 + nj * 8 + qc;
            float2 v0 = make_float2(acc[mi][nj][0], acc[mi][nj][1]);
            float2 v1 = make_float2(acc[mi][nj][2], acc[mi][nj][3]);
            *(float2*)(Ob + (size_t)row * D_DIM + col) = v0;
            *(float2*)(Ob + (size_t)(row + 8) * D_DIM + col) = v1;
        }
    }
}

// -------------------------------------------------------------------------
extern "C" void kernel_launch(void* const* d_in, const int* in_sizes, int n_in,
                              void* d_out, int out_size)
{
    const float* q = (const float*)d_in[0];
    const float* k = (const float*)d_in[1];
    const float* v = (const float*)d_in[2];

    float* outp = (float*)d_out;                                   // BH*S*D
    float* attn = outp + (size_t)BH * S_LEN * D_DIM;               // BH*S*S
    float* tau  = attn + SELEM;                                    // BH*S

    cudaFuncSetAttribute(dsa_scores_kernel,
                         cudaFuncAttributeMaxDynamicSharedMemorySize, SC_SMEM);
    cudaFuncSetAttribute(dsa_av_tf32,
                         cudaFuncAttributeMaxDynamicSharedMemorySize, AVT_SMEM);

    dsa_prep<<<2048, 256>>>(q, k, v);
    dsa_scores_kernel<<<dim3(S_LEN / 128, BH), 512, SC_SMEM>>>(attn);
    dsa_softvar_kernel<<<BH * S_LEN / 8, 256>>>(attn, tau);
    dsa_av_tf32<<<dim3(S_LEN / 128, BH), 256, AVT_SMEM>>>(attn, outp);
}